// round 8
// baseline (speedup 1.0000x reference)
#include <cuda_runtime.h>

// HysteresisThresholding 2048x2048. Two kernels:
//  1) pack:  thresholds (low/high outputs) + word-packed weak/strong masks
//  2) flood: persistent, 1 block/SM; each band converges an 8-row-fat-halo
//            extended region locally in smem (~2 global passes); final
//            output fused at the end. Row guards for the partial last band.

#define H_IMG 2048
#define W_IMG 2048
#define WX 64
#define QX 512
#define N_WORDS (H_IMG * WX)
#define N_PIX (H_IMG * W_IMG)
#define N_QUAD (N_PIX / 4)
#define LOW_T 0.3f
#define HIGH_T 0.7f
#define MAX_PASS 64
#define ROWS_PER 14              // 147 bands (last band partial: 4 rows)
#define EXT 8                    // fat halo rows each side
#define ITER_ROWS (ROWS_PER + 2 * EXT)          // 30 iterated rows
#define ACT_ROWS (ITER_ROWS + 4)                // +2 context rows each side
#define NT 1024

__device__ unsigned g_active[N_WORDS];
__device__ unsigned g_w1[N_WORDS];
__device__ unsigned g_w2[N_WORDS];
__device__ volatile unsigned g_arrive[256];
__device__ volatile unsigned g_release;

// ---------------- kernel 1: thresholds + mask pack ----------------
__global__ void __launch_bounds__(256)
pack_kernel(const float4* __restrict__ thin4, float* __restrict__ out) {
    int qg = blockIdx.x * 256 + threadIdx.x;
    unsigned lane = threadIdx.x & 31u;
    const unsigned nsh   = (lane & 7u) * 4u;
    const unsigned gmask = 0xFFu << (lane & 24u);

    float4* low4  = (float4*)out;
    float4* high4 = (float4*)(out + N_PIX);

    float4 v = thin4[qg];
    float4 lo, hi;
    lo.x = (v.x < LOW_T)  ? 0.0f : v.x;  hi.x = (v.x < HIGH_T) ? 0.0f : v.x;
    lo.y = (v.y < LOW_T)  ? 0.0f : v.y;  hi.y = (v.y < HIGH_T) ? 0.0f : v.y;
    lo.z = (v.z < LOW_T)  ? 0.0f : v.z;  hi.z = (v.z < HIGH_T) ? 0.0f : v.z;
    lo.w = (v.w < LOW_T)  ? 0.0f : v.w;  hi.w = (v.w < HIGH_T) ? 0.0f : v.w;
    low4[qg]  = lo;
    high4[qg] = hi;

    unsigned nw = (v.x >= LOW_T ? 1u : 0u) | (v.y >= LOW_T ? 2u : 0u)
                | (v.z >= LOW_T ? 4u : 0u) | (v.w >= LOW_T ? 8u : 0u);
    unsigned ns = (v.x >= HIGH_T ? 1u : 0u) | (v.y >= HIGH_T ? 2u : 0u)
                | (v.z >= HIGH_T ? 4u : 0u) | (v.w >= HIGH_T ? 8u : 0u);
    unsigned wk = __reduce_or_sync(gmask, nw << nsh);
    unsigned ac = __reduce_or_sync(gmask, ns << nsh);

    if ((lane & 7u) == 0u) {
        int gw = qg >> 3;
        int r = gw >> 6, wx = gw & 63;
        unsigned t1c = (wx == 0) ? 0xFFFFFFFEu : (wx == WX - 1) ? 0x3FFFFFFFu : 0xFFFFFFFFu;
        unsigned t1r = (r >= 1 && r <= H_IMG - 3) ? 0xFFFFFFFFu : 0u;
        unsigned t2c = (wx == 0) ? 0xFFFFFFFCu : (wx == WX - 1) ? 0x1FFFFFFFu : 0xFFFFFFFFu;
        unsigned t2r = (r >= 2 && r <= H_IMG - 4) ? 0xFFFFFFFFu : 0u;
        g_w1[gw]     = wk & t1c & t1r;
        g_w2[gw]     = wk & t2c & t2r;
        g_active[gw] = ac;
    }

    if (blockIdx.x == 0) {
        if (threadIdx.x < 256) g_arrive[threadIdx.x] = 0u;
        if (threadIdx.x == 0) g_release = 0u;
    }
}

// ---------------- kernel 2: fat-halo flood + fused final ----------------
__global__ void __launch_bounds__(NT, 1)
flood_kernel(const float4* __restrict__ thin4, float* __restrict__ out,
             unsigned nblocks) {
    __shared__ unsigned s_act[ACT_ROWS * WX];
    __shared__ unsigned s_w1[ITER_ROWS * WX];
    __shared__ unsigned s_w2[ITER_ROWS * WX];
    __shared__ unsigned s_any;

    const int tid = threadIdx.x;
    const int bid = blockIdx.x;
    const int r0  = bid * ROWS_PER;                 // first owned row
    const int er0 = r0 - EXT;                       // first iterated row (virtual)
    const int a0  = er0 - 2;                        // first act context row (virtual)

    // ---- initial load ----
    for (int i = tid; i < ACT_ROWS * WX; i += NT) {
        int gr = a0 + (i >> 6), wx = i & 63;
        unsigned v = 0u;
        if ((unsigned)gr < (unsigned)H_IMG) v = __ldcg(&g_active[gr * WX + wx]);
        s_act[i] = v;
    }
    for (int i = tid; i < ITER_ROWS * WX; i += NT) {
        int gr = er0 + (i >> 6), wx = i & 63;
        unsigned a = 0u, b = 0u;
        if ((unsigned)gr < (unsigned)H_IMG) {
            a = __ldcg(&g_w1[gr * WX + wx]);
            b = __ldcg(&g_w2[gr * WX + wx]);
        }
        s_w1[i] = a; s_w2[i] = b;
    }
    __syncthreads();

    // owned-slot validity (unique thread slot per owned word, row must exist)
    const int i0 = tid, i1 = tid + NT;
    const bool own0 = (i0 >= EXT * WX) && (i0 < (EXT + ROWS_PER) * WX)
                      && (er0 + (i0 >> 6)) < H_IMG;
    const bool own1 = (i1 < ITER_ROWS * WX) && (i1 >= EXT * WX)
                      && (i1 < (EXT + ROWS_PER) * WX) && (er0 + (i1 >> 6)) < H_IMG;

    unsigned gen = 0;
    for (int pass = 0; pass < MAX_PASS; pass++) {
        unsigned old0 = own0 ? s_act[i0 + 2 * WX] : 0u;
        unsigned old1 = own1 ? s_act[i1 + 2 * WX] : 0u;

        // ---- converge extended region locally ----
        for (;;) {
            bool ch = false;
            #pragma unroll
            for (int half = 0; half < 2; half++) {
                int i = tid + half * NT;
                if (i >= ITER_ROWS * WX) break;
                int wx = i & 63;
                int sr = (i >> 6) + 2;
                unsigned c  = s_act[sr * WX + wx];
                unsigned w1 = s_w1[i];
                unsigned w2 = s_w2[i];
                unsigned todo = (w1 | w2) & ~c;
                if (!todo) continue;
                auto S = [&](int r_, int x_) -> unsigned {
                    return ((unsigned)x_ < (unsigned)WX) ? s_act[r_ * WX + x_] : 0u;
                };
                unsigned l  = S(sr, wx - 1),      rr = S(sr, wx + 1);
                unsigned u1 = S(sr - 1, wx), u1l = S(sr - 1, wx - 1), u1r = S(sr - 1, wx + 1);
                unsigned d1 = S(sr + 1, wx), d1l = S(sr + 1, wx - 1), d1r = S(sr + 1, wx + 1);
                unsigned conn1 =
                      u1 | __funnelshift_l(u1l, u1, 1) | __funnelshift_r(u1, u1r, 1)
                    |      __funnelshift_l(l,   c,  1) | __funnelshift_r(c,  rr,  1)
                    | d1 | __funnelshift_l(d1l, d1, 1) | __funnelshift_r(d1, d1r, 1);
                unsigned nw2 = c | (w1 & conn1);
                if (w2 & ~nw2) {
                    unsigned u2 = S(sr - 2, wx), u2l = S(sr - 2, wx - 1), u2r = S(sr - 2, wx + 1);
                    unsigned d2 = S(sr + 2, wx), d2l = S(sr + 2, wx - 1), d2r = S(sr + 2, wx + 1);
                    unsigned conn2 =
                          u2 | __funnelshift_l(u2l, u2, 2) | __funnelshift_r(u2, u2r, 2)
                        |      __funnelshift_l(l,   c,  2) | __funnelshift_r(c,  rr,  2)
                        | d2 | __funnelshift_l(d2l, d2, 2) | __funnelshift_r(d2, d2r, 2);
                    nw2 |= w2 & conn2;
                }
                #pragma unroll
                for (int k = 0; k < 5; k++) {
                    unsigned sp = nw2;
                    nw2 |= (w1 & ((sp << 1) | (sp >> 1)))
                         | (w2 & ((sp << 2) | (sp >> 2)));
                }
                if (nw2 != c) { s_act[sr * WX + wx] = nw2; ch = true; }
            }
            if (!__syncthreads_or(ch ? 1 : 0)) break;
        }

        // ---- detect owned-region change + write back (guarded) ----
        bool owned_ch = false;
        if (own0) {
            unsigned nv = s_act[i0 + 2 * WX];
            if (nv != old0) {
                owned_ch = true;
                __stcg(&g_active[(er0 + (i0 >> 6)) * WX + (i0 & 63)], nv);
            }
        }
        if (own1) {
            unsigned nv = s_act[i1 + 2 * WX];
            if (nv != old1) {
                owned_ch = true;
                __stcg(&g_active[(er0 + (i1 >> 6)) * WX + (i1 & 63)], nv);
            }
        }
        unsigned band_changed = __syncthreads_or(owned_ch ? 1 : 0);

        // ---- grid barrier with embedded any-changed ----
        gen++;
        if (tid == 0) {
            __threadfence();
            g_arrive[bid] = (gen << 1) | (band_changed ? 1u : 0u);
        }
        if (bid == 0) {
            unsigned myany = 0u;
            if (tid < (int)nblocks) {
                unsigned v;
                while (((v = g_arrive[tid]) >> 1) < gen) __nanosleep(32);
                myany = v & 1u;
            }
            unsigned any = __syncthreads_or(myany);
            if (tid == 0) { __threadfence(); g_release = (gen << 1) | any; }
        }
        if (tid == 0) {
            unsigned v;
            while (((v = g_release) >> 1) < gen) __nanosleep(32);
            s_any = v & 1u;
            __threadfence();
        }
        __syncthreads();
        if (!s_any) break;

        // ---- reload halo act rows (owned rows stay authoritative) ----
        for (int i = tid; i < ACT_ROWS * WX; i += NT) {
            int ar = i >> 6;
            if (ar >= EXT + 2 && ar < EXT + 2 + ROWS_PER) continue;
            int gr = a0 + ar, wx = i & 63;
            unsigned v = 0u;
            if ((unsigned)gr < (unsigned)H_IMG) v = __ldcg(&g_active[gr * WX + wx]);
            s_act[i] = v;
        }
        __syncthreads();
    }

    // ---- fused final output for owned band (guarded) ----
    float4* final4 = (float4*)(out + 2 * N_PIX);
    const int nrows_own = min(H_IMG - r0, ROWS_PER);
    const int nq = nrows_own * QX;
    for (int j = tid; j < nq; j += NT) {
        int row = j >> 9;
        int qc  = j & 511;
        unsigned word = s_act[(row + EXT + 2) * WX + (qc >> 3)];
        unsigned bits = word >> ((qc & 7u) * 4u);
        int qg = (r0 + row) * QX + qc;
        float4 v = __ldg(&thin4[qg]);
        float4 f;
        f.x = (bits & 1u) ? v.x : 0.0f;
        f.y = (bits & 2u) ? v.y : 0.0f;
        f.z = (bits & 4u) ? v.z : 0.0f;
        f.w = (bits & 8u) ? v.w : 0.0f;
        final4[qg] = f;
    }
}

extern "C" void kernel_launch(void* const* d_in, const int* in_sizes, int n_in,
                              void* d_out, int out_size) {
    const float* thin = (const float*)d_in[0];
    float* out = (float*)d_out;
    (void)in_sizes; (void)n_in; (void)out_size;

    unsigned fgrid = (H_IMG + ROWS_PER - 1) / ROWS_PER;   // 147

    pack_kernel<<<N_QUAD / 256, 256>>>((const float4*)thin, out);
    flood_kernel<<<fgrid, NT>>>((const float4*)thin, out, fgrid);
}

// round 9
// speedup vs baseline: 1.3649x; 1.3649x over previous
#include <cuda_runtime.h>

// HysteresisThresholding 2048x2048. Single persistent kernel, 1 block/SM:
//  phase 1: thresholds (low/high) + word-packed weak/strong masks (from
//           cp.async-staged smem copy of thin)
//  phase 2: band-local (14-row) smem flood fill to fixed point; light
//           flag-array grid barrier with embedded any-changed bit
//  phase 3: final = active ? thin : 0, from smem (zero global loads)

#define H_IMG 2048
#define W_IMG 2048
#define WX 64
#define QX 512
#define N_WORDS (H_IMG * WX)
#define N_PIX (H_IMG * W_IMG)
#define LOW_T 0.3f
#define HIGH_T 0.7f
#define MAX_PASS 64
#define ROWS_PER 14              // 147 bands, last band 4 rows
#define NT 1024

// dynamic smem layout (unsigned words)
#define SA_OFF 0                                   // s_act: (ROWS_PER+4)*WX
#define W1_OFF ((ROWS_PER + 4) * WX)
#define W2_OFF (W1_OFF + ROWS_PER * WX)
#define TH_OFF (W2_OFF + ROWS_PER * WX)            // s_thin: ROWS_PER*QX float4
#define SMEM_WORDS (TH_OFF + ROWS_PER * QX * 4)
#define SMEM_BYTES (SMEM_WORDS * 4)

__device__ unsigned g_active[N_WORDS];
__device__ volatile unsigned g_arrive[256];
__device__ volatile unsigned g_release;

__device__ __forceinline__ void cp_async16(void* sdst, const void* gsrc) {
    unsigned saddr = (unsigned)__cvta_generic_to_shared(sdst);
    asm volatile("cp.async.cg.shared.global [%0], [%1], 16;\n"
                 :: "r"(saddr), "l"(gsrc) : "memory");
}

__global__ void __launch_bounds__(NT, 1)
hyst_kernel(const float4* __restrict__ thin4, float* __restrict__ out,
            unsigned nblocks) {
    extern __shared__ unsigned smem[];
    unsigned* s_act = smem + SA_OFF;
    unsigned* s_w1  = smem + W1_OFF;
    unsigned* s_w2  = smem + W2_OFF;
    float4*   s_th  = (float4*)(smem + TH_OFF);
    __shared__ unsigned s_any;
    __shared__ unsigned s_gbase;

    const int tid  = threadIdx.x;
    const int bid  = blockIdx.x;
    const int lane = tid & 31;
    const int r0   = bid * ROWS_PER;
    const int nrows  = min(H_IMG - r0, ROWS_PER);
    const int nwords = nrows * WX;                  // <= 896
    const int nquads = nrows * QX;

    float4* low4   = (float4*)out;
    float4* high4  = (float4*)(out + N_PIX);
    float4* final4 = (float4*)(out + 2 * N_PIX);

    const unsigned nsh   = (lane & 7u) * 4u;
    const unsigned gmask = 0xFFu << (lane & 24u);

    // cross-replay-safe barrier generation base
    if (tid == 0) s_gbase = g_release >> 1;

    // -------- stage thin into smem --------
    for (int j = tid; j < nquads; j += NT)
        cp_async16(&s_th[j], &thin4[r0 * QX + j]);
    asm volatile("cp.async.commit_group;\n");
    for (int i = tid; i < (ROWS_PER + 4) * WX; i += NT) s_act[i] = 0u;
    asm volatile("cp.async.wait_group 0;\n" ::: "memory");
    __syncthreads();
    unsigned gen = s_gbase;

    // -------- Phase 1: thresholds + masks --------
    for (int j = tid; j < nquads; j += NT) {
        float4 v = s_th[j];
        float4 lo, hi;
        lo.x = (v.x < LOW_T)  ? 0.0f : v.x;  hi.x = (v.x < HIGH_T) ? 0.0f : v.x;
        lo.y = (v.y < LOW_T)  ? 0.0f : v.y;  hi.y = (v.y < HIGH_T) ? 0.0f : v.y;
        lo.z = (v.z < LOW_T)  ? 0.0f : v.z;  hi.z = (v.z < HIGH_T) ? 0.0f : v.z;
        lo.w = (v.w < LOW_T)  ? 0.0f : v.w;  hi.w = (v.w < HIGH_T) ? 0.0f : v.w;
        int qg = r0 * QX + j;
        low4[qg]  = lo;
        high4[qg] = hi;

        unsigned nw = (v.x >= LOW_T ? 1u : 0u) | (v.y >= LOW_T ? 2u : 0u)
                    | (v.z >= LOW_T ? 4u : 0u) | (v.w >= LOW_T ? 8u : 0u);
        unsigned ns = (v.x >= HIGH_T ? 1u : 0u) | (v.y >= HIGH_T ? 2u : 0u)
                    | (v.z >= HIGH_T ? 4u : 0u) | (v.w >= HIGH_T ? 8u : 0u);
        unsigned wk = __reduce_or_sync(gmask, nw << nsh);
        unsigned ac = __reduce_or_sync(gmask, ns << nsh);

        if ((lane & 7) == 0) {
            int w  = j >> 3;
            int gw = r0 * WX + w;
            int r = gw >> 6, wx = gw & 63;
            unsigned t1c = (wx == 0) ? 0xFFFFFFFEu : (wx == WX - 1) ? 0x3FFFFFFFu : 0xFFFFFFFFu;
            unsigned t1r = (r >= 1 && r <= H_IMG - 3) ? 0xFFFFFFFFu : 0u;
            unsigned t2c = (wx == 0) ? 0xFFFFFFFCu : (wx == WX - 1) ? 0x1FFFFFFFu : 0xFFFFFFFFu;
            unsigned t2r = (r >= 2 && r <= H_IMG - 4) ? 0xFFFFFFFFu : 0u;
            s_w1[w] = wk & t1c & t1r;
            s_w2[w] = wk & t2c & t2r;
            s_act[((w >> 6) + 2) * WX + wx] = ac;
            __stcg(&g_active[gw], ac);
        }
    }

    // barrier 1 (publish masks/active)
    {
        gen++;
        __syncthreads();
        if (tid == 0) { __threadfence(); g_arrive[bid] = gen << 1; }
        if (bid == 0) {
            if (tid < (int)nblocks) {
                unsigned v;
                while (((v = g_arrive[tid]) >> 1) < gen) __nanosleep(32);
            }
            __syncthreads();
            if (tid == 0) { __threadfence(); g_release = (gen << 1) | 1u; }
        }
        if (tid == 0) {
            while ((g_release >> 1) < gen) __nanosleep(32);
            __threadfence();
        }
        __syncthreads();
    }

    // -------- Phase 2: flood fill --------
    for (int pass = 0; pass < MAX_PASS; pass++) {
        // reload 4 halo rows
        for (int i = tid; i < 4 * WX; i += NT) {
            int hr = i >> 6, wx = i & 63;
            int gr = (hr < 2) ? (r0 - 2 + hr) : (r0 + nrows + (hr - 2));
            int sr = (hr < 2) ? hr : (nrows + hr);
            unsigned v = 0u;
            if ((unsigned)gr < (unsigned)H_IMG) v = __ldcg(&g_active[gr * WX + wx]);
            s_act[sr * WX + wx] = v;
        }
        __syncthreads();

        bool band_changed = false;
        for (;;) {
            bool ch = false;
            if (tid < nwords) {
                int wx = tid & 63;
                int sr = (tid >> 6) + 2;
                unsigned c  = s_act[sr * WX + wx];
                unsigned w1 = s_w1[tid];
                unsigned w2 = s_w2[tid];
                unsigned todo = (w1 | w2) & ~c;
                if (todo) {
                    auto S = [&](int r_, int x_) -> unsigned {
                        return ((unsigned)x_ < (unsigned)WX) ? s_act[r_ * WX + x_] : 0u;
                    };
                    unsigned l  = S(sr, wx - 1),      rr = S(sr, wx + 1);
                    unsigned u1 = S(sr - 1, wx), u1l = S(sr - 1, wx - 1), u1r = S(sr - 1, wx + 1);
                    unsigned d1 = S(sr + 1, wx), d1l = S(sr + 1, wx - 1), d1r = S(sr + 1, wx + 1);
                    unsigned conn1 =
                          u1 | __funnelshift_l(u1l, u1, 1) | __funnelshift_r(u1, u1r, 1)
                        |      __funnelshift_l(l,   c,  1) | __funnelshift_r(c,  rr,  1)
                        | d1 | __funnelshift_l(d1l, d1, 1) | __funnelshift_r(d1, d1r, 1);
                    unsigned nw2 = c | (w1 & conn1);
                    if (w2 & ~nw2) {
                        unsigned u2 = S(sr - 2, wx), u2l = S(sr - 2, wx - 1), u2r = S(sr - 2, wx + 1);
                        unsigned d2 = S(sr + 2, wx), d2l = S(sr + 2, wx - 1), d2r = S(sr + 2, wx + 1);
                        unsigned conn2 =
                              u2 | __funnelshift_l(u2l, u2, 2) | __funnelshift_r(u2, u2r, 2)
                            |      __funnelshift_l(l,   c,  2) | __funnelshift_r(c,  rr,  2)
                            | d2 | __funnelshift_l(d2l, d2, 2) | __funnelshift_r(d2, d2r, 2);
                        nw2 |= w2 & conn2;
                    }
                    #pragma unroll
                    for (int k = 0; k < 5; k++) {
                        unsigned sp = nw2;
                        nw2 |= (w1 & ((sp << 1) | (sp >> 1)))
                             | (w2 & ((sp << 2) | (sp >> 2)));
                    }
                    if (nw2 != c) { s_act[sr * WX + wx] = nw2; ch = true; }
                }
            }
            if (!__syncthreads_or(ch ? 1 : 0)) break;
            band_changed = true;
        }

        if (band_changed && tid < nwords)
            __stcg(&g_active[r0 * WX + tid],
                   s_act[((tid >> 6) + 2) * WX + (tid & 63)]);

        // grid barrier with embedded any-changed
        gen++;
        __syncthreads();
        if (tid == 0) {
            __threadfence();
            g_arrive[bid] = (gen << 1) | (band_changed ? 1u : 0u);
        }
        if (bid == 0) {
            unsigned myany = 0u;
            if (tid < (int)nblocks) {
                unsigned v;
                while (((v = g_arrive[tid]) >> 1) < gen) __nanosleep(32);
                myany = v & 1u;
            }
            unsigned any = __syncthreads_or(myany);
            if (tid == 0) { __threadfence(); g_release = (gen << 1) | any; }
        }
        if (tid == 0) {
            unsigned v;
            while (((v = g_release) >> 1) < gen) __nanosleep(32);
            s_any = v & 1u;
            __threadfence();
        }
        __syncthreads();
        if (!s_any) break;
    }

    // -------- Phase 3: final output (smem only) --------
    for (int j = tid; j < nquads; j += NT) {
        int w = j >> 3;
        unsigned word = s_act[((w >> 6) + 2) * WX + (w & 63)];
        unsigned bits = word >> nsh;
        float4 v = s_th[j];
        float4 f;
        f.x = (bits & 1u) ? v.x : 0.0f;
        f.y = (bits & 2u) ? v.y : 0.0f;
        f.z = (bits & 4u) ? v.z : 0.0f;
        f.w = (bits & 8u) ? v.w : 0.0f;
        final4[r0 * QX + j] = f;
    }
}

extern "C" void kernel_launch(void* const* d_in, const int* in_sizes, int n_in,
                              void* d_out, int out_size) {
    const float* thin = (const float*)d_in[0];
    float* out = (float*)d_out;
    (void)in_sizes; (void)n_in; (void)out_size;

    static int attr_done = 0;
    if (!attr_done) {
        cudaFuncSetAttribute(hyst_kernel,
                             cudaFuncAttributeMaxDynamicSharedMemorySize, SMEM_BYTES);
        attr_done = 1;
    }

    unsigned grid = (H_IMG + ROWS_PER - 1) / ROWS_PER;   // 147

    hyst_kernel<<<grid, NT, SMEM_BYTES>>>((const float4*)thin, out, grid);
}